// round 16
// baseline (speedup 1.0000x reference)
#include <cuda_runtime.h>
#include <math.h>
#include <stdint.h>

#define B_   16
#define TO_  2048
#define TI_  2048
#define D_   64
#define BM   128
#define BN   64
#define NTH  256
#define NT   (TI_/BN)

// smem layout (bytes):
//  K buf0 @ 0      : 64 rows * 272B = 17408   (ldmatrix conflict-free)
//  K buf1 @ 17408  : 17408
//  V-orig @ 34816  : 64 rows * 256B = 16384   (raw [kv][d], single buffer)
//  V^T    @ 51200  : 64 rows * 272B = 17408   ([d][kv], ldmatrix conflict-free)
//  mask   @ 68608  : 128 rows * 272B = 34816
#define KSTR   272
#define KT     17408
#define VORIG  34816
#define VT     51200
#define VTSTR  272
#define SM_M   68608
#define SMEM_BYTES (68608 + 34816)   // 103424

#define QSCALE 0.18033688011112042f  // 0.125 * log2(e)

#define CPA16(dst, src) asm volatile("cp.async.cg.shared.global [%0], [%1], 16;" :: "r"(dst), "l"(src))
#define CPA_COMMIT()    asm volatile("cp.async.commit_group;" ::: "memory")
#define CPA_WAIT(n)     asm volatile("cp.async.wait_group %0;" :: "n"(n) : "memory")

static __device__ __forceinline__ uint32_t smem_u32(const void* p) {
    uint32_t a;
    asm("{ .reg .u64 t; cvta.to.shared.u64 t, %1; cvt.u32.u64 %0, t; }" : "=r"(a) : "l"(p));
    return a;
}
static __device__ __forceinline__ uint32_t tf32rna(float x) {
    uint32_t r; asm("cvt.rna.tf32.f32 %0, %1;" : "=r"(r) : "f"(x)); return r;
}
static __device__ __forceinline__ float ex2f(float x) {
    float y; asm("ex2.approx.ftz.f32 %0, %1;" : "=f"(y) : "f"(x)); return y;
}
static __device__ __forceinline__ float ldsf(uint32_t a) {
    float v; asm volatile("ld.shared.f32 %0, [%1];" : "=f"(v) : "r"(a)); return v;
}
static __device__ __forceinline__ int2 lds64i(uint32_t a) {
    int2 v; asm volatile("ld.shared.v2.b32 {%0,%1}, [%2];" : "=r"(v.x), "=r"(v.y) : "r"(a)); return v;
}
static __device__ __forceinline__ float4 lds128f(uint32_t a) {
    float4 v;
    asm volatile("ld.shared.v4.f32 {%0,%1,%2,%3}, [%4];"
                 : "=f"(v.x), "=f"(v.y), "=f"(v.z), "=f"(v.w) : "r"(a));
    return v;
}
static __device__ __forceinline__ void sts128u(uint32_t a, uint32_t x, uint32_t y,
                                               uint32_t z, uint32_t w) {
    asm volatile("st.shared.v4.b32 [%0], {%1,%2,%3,%4};"
                 :: "r"(a), "r"(x), "r"(y), "r"(z), "r"(w) : "memory");
}
static __device__ __forceinline__ void ldm4(uint32_t& r0, uint32_t& r1, uint32_t& r2,
                                            uint32_t& r3, uint32_t a) {
    asm volatile("ldmatrix.sync.aligned.m8n8.x4.shared.b16 {%0,%1,%2,%3}, [%4];"
                 : "=r"(r0), "=r"(r1), "=r"(r2), "=r"(r3) : "r"(a));
}
static __device__ __forceinline__ void mma_tf32(float* c, uint32_t a0, uint32_t a1,
                                                uint32_t a2, uint32_t a3,
                                                uint32_t b0, uint32_t b1) {
    asm volatile(
        "mma.sync.aligned.m16n8k8.row.col.f32.tf32.tf32.f32 "
        "{%0,%1,%2,%3}, {%4,%5,%6,%7}, {%8,%9}, {%0,%1,%2,%3};"
        : "+f"(c[0]), "+f"(c[1]), "+f"(c[2]), "+f"(c[3])
        : "r"(a0), "r"(a1), "r"(a2), "r"(a3), "r"(b0), "r"(b1));
}

__global__ __launch_bounds__(NTH, 2)
void attn_hmma(const float* __restrict__ Q, const float* __restrict__ K,
               const float* __restrict__ V, const int* __restrict__ M,
               float* __restrict__ O)
{
    extern __shared__ char smem[];
    const uint32_t sb = smem_u32(smem);
    const int tid  = threadIdx.x;
    const int w    = tid >> 5;
    const int lane = tid & 31;
    const int q4   = lane & 3;        // quad lane
    const int r4   = lane >> 2;       // 0..7
    const int b    = blockIdx.y;
    const int q0   = blockIdx.x * BM;

    const float* Qb = Q + ((size_t)b * TO_ + q0) * D_;
    const float* Kb = K + (size_t)b * TI_ * D_;
    const float* Vb = V + (size_t)b * TI_ * D_;
    const int*   Mb = M + ((size_t)b * TO_ + q0) * TI_;
    float*       Ob = O + ((size_t)b * TO_ + q0) * D_;

    // ---- stage K(0)->buf0, V(0)->V-orig ----
#pragma unroll
    for (int i = 0; i < 4; i++) {
        int idx = tid + i * NTH;            // 0..1023 chunk ids
        int row = idx >> 4;
        int c4  = idx & 15;
        CPA16(sb + row * KSTR + c4 * 16,          (const char*)(Kb + (size_t)row * D_) + c4 * 16);
        CPA16(sb + VORIG + row * 256 + c4 * 16,   (const char*)(Vb + (size_t)row * D_) + c4 * 16);
    }
    CPA_COMMIT();

    // ---- Q fragments (once, scale*log2e folded, tf32 rna) ----
    uint32_t qa[8][4];
    {
        const float* qp = Qb + (size_t)(w * 16 + r4) * D_ + q4;
#pragma unroll
        for (int kf = 0; kf < 8; kf++) {
            qa[kf][0] = tf32rna(QSCALE * qp[kf * 8]);
            qa[kf][1] = tf32rna(QSCALE * qp[kf * 8 + 8 * D_]);
            qa[kf][2] = tf32rna(QSCALE * qp[kf * 8 + 4]);
            qa[kf][3] = tf32rna(QSCALE * qp[kf * 8 + 4 + 8 * D_]);
        }
    }

    float oc[8][4];
#pragma unroll
    for (int nf = 0; nf < 8; nf++)
#pragma unroll
        for (int i = 0; i < 4; i++) oc[nf][i] = 0.f;
    float l0 = 0.f, l1 = 0.f;

    // GEMM1 ldmatrix per-thread row (272B stride, conflict-free)
    const uint32_t ldmc = (uint32_t)(lane & 7) * KSTR + (uint32_t)((lane >> 3) & 1) * 16
                        + (uint32_t)(lane >> 4) * (8 * KSTR);

    // transpose assignment: d = 32*(w&1)+lane, kv quarter = 16*(w>>1)
    const int tr_d   = 32 * (w & 1) + lane;
    const int tr_kvq = 16 * (w >> 1);
    const uint32_t tr_dst_row = sb + VT + (uint32_t)tr_d * VTSTR;
    const uint32_t tr_src_col = sb + VORIG + (uint32_t)tr_d * 4;

    // GEMM2 ldmatrix per-lane geometry: matrix m = lane>>3 -> (nf = 2*nfp + (m>>1), half = m&1)
    const int g2_m  = lane >> 3;
    const int g2_r  = lane & 7;
    const uint32_t g2_half16 = (uint32_t)(g2_m & 1) * 16;
    const int g2_nfoff = g2_m >> 1;       // 0 or 1

    CPA_WAIT(0);
    // K(0) rewrite to tf32-rna (own chunks)
#pragma unroll
    for (int i = 0; i < 4; i++) {
        int idx = tid + i * NTH;
        uint32_t ak = sb + (idx >> 4) * KSTR + (idx & 15) * 16;
        float4 f = lds128f(ak);
        sts128u(ak, tf32rna(f.x), tf32rna(f.y), tf32rna(f.z), tf32rna(f.w));
    }
    __syncthreads();                      // V-orig(0) visible to all
    // transpose V(0) -> V^T (with rna)
#pragma unroll
    for (int i = 0; i < 4; i++) {
        int kvb = tr_kvq + 4 * i;
        uint32_t s = tr_src_col + (uint32_t)kvb * 256;
        float f0 = ldsf(s), f1 = ldsf(s + 256), f2 = ldsf(s + 512), f3 = ldsf(s + 768);
        sts128u(tr_dst_row + (uint32_t)kvb * 4,
                tf32rna(f0), tf32rna(f1), tf32rna(f2), tf32rna(f3));
    }
    __syncthreads();                      // K-rewrite + V^T(0) published

    for (int t = 0; t < NT; t++) {
        const uint32_t sK = sb + (uint32_t)(t & 1) * KT;

        // ---- stage mask(t) — group ----
        {
            const char* Mg = (const char*)(Mb + (size_t)t * BN);
#pragma unroll
            for (int i = 0; i < 8; i++) {
                int chunk = tid + i * NTH;   // 128 rows x 16 chunks
                int row = chunk >> 4;
                int c4  = chunk & 15;
                CPA16(sb + SM_M + row * 272 + c4 * 16, Mg + (size_t)row * (TI_ * 4) + c4 * 16);
            }
        }
        CPA_COMMIT();
        // ---- stage K(t+1) — group ----
        if (t + 1 < NT) {
            const uint32_t sKn = sb + (uint32_t)((t + 1) & 1) * KT;
            const float* Kg = Kb + (size_t)(t + 1) * BN * D_;
#pragma unroll
            for (int i = 0; i < 4; i++) {
                int idx = tid + i * NTH;
                CPA16(sKn + (idx >> 4) * KSTR + (idx & 15) * 16,
                      (const char*)(Kg + (size_t)(idx >> 4) * D_) + (idx & 15) * 16);
            }
        }
        CPA_COMMIT();

        // ---- GEMM1: S = Q K^T (ldmatrix.x4) ----
        float sc[8][4];
#pragma unroll
        for (int nf = 0; nf < 8; nf++)
#pragma unroll
            for (int i = 0; i < 4; i++) sc[nf][i] = 0.f;

#pragma unroll
        for (int kf = 0; kf < 8; kf++) {
#pragma unroll
            for (int nfp = 0; nfp < 4; nfp++) {
                uint32_t b0, b1, b2, b3;
                ldm4(b0, b1, b2, b3, sK + ldmc + (uint32_t)nfp * (16 * KSTR) + (uint32_t)kf * 32);
                mma_tf32(sc[2 * nfp],     qa[kf][0], qa[kf][1], qa[kf][2], qa[kf][3], b0, b1);
                mma_tf32(sc[2 * nfp + 1], qa[kf][0], qa[kf][1], qa[kf][2], qa[kf][3], b2, b3);
            }
        }

        CPA_WAIT(1);          // mask staged (K prefetch may be in flight)
        __syncthreads();      // sync A: mask + last V^T/K-rewrite visible

        // ---- stage V(t+1) -> V-orig (race-free: after sync A) ----
        if (t + 1 < NT) {
            const float* Vg = Vb + (size_t)(t + 1) * BN * D_;
#pragma unroll
            for (int i = 0; i < 4; i++) {
                int idx = tid + i * NTH;
                CPA16(sb + VORIG + (idx >> 4) * 256 + (idx & 15) * 16,
                      (const char*)(Vg + (size_t)(idx >> 4) * D_) + (idx & 15) * 16);
            }
        }
        CPA_COMMIT();

        // ---- mask + exp2 + tf32-rna (l from ROUNDED p) ----
        {
            const uint32_t mbase = sb + SM_M + (uint32_t)(w * 16 + r4) * 272 + (uint32_t)(2 * q4) * 4;
#pragma unroll
            for (int nf = 0; nf < 8; nf++) {
                const uint32_t ma = mbase + nf * 32;
                const int2 mlo = lds64i(ma);
                const int2 mhi = lds64i(ma + 8 * 272);
                float p0 = (mlo.x != 0) ? ex2f(sc[nf][0]) : 0.f;
                float p1 = (mlo.y != 0) ? ex2f(sc[nf][1]) : 0.f;
                float p2 = (mhi.x != 0) ? ex2f(sc[nf][2]) : 0.f;
                float p3 = (mhi.y != 0) ? ex2f(sc[nf][3]) : 0.f;
                p0 = __uint_as_float(tf32rna(p0));
                p1 = __uint_as_float(tf32rna(p1));
                p2 = __uint_as_float(tf32rna(p2));
                p3 = __uint_as_float(tf32rna(p3));
                l0 += p0 + p1;
                l1 += p2 + p3;
                sc[nf][0] = p0; sc[nf][1] = p1; sc[nf][2] = p2; sc[nf][3] = p3;
            }
        }

        // ---- P C-frag -> A-frag permutation (in place, all kf) ----
        {
            const int s0 = (lane & ~3) | (q4 >> 1);
            const int s2 = s0 + 2;
            const bool odd = (q4 & 1) != 0;
#pragma unroll
            for (int kf = 0; kf < 8; kf++) {
                float t00 = __shfl_sync(0xffffffffu, sc[kf][0], s0);
                float t01 = __shfl_sync(0xffffffffu, sc[kf][1], s0);
                float t10 = __shfl_sync(0xffffffffu, sc[kf][2], s0);
                float t11 = __shfl_sync(0xffffffffu, sc[kf][3], s0);
                float t20 = __shfl_sync(0xffffffffu, sc[kf][0], s2);
                float t21 = __shfl_sync(0xffffffffu, sc[kf][1], s2);
                float t30 = __shfl_sync(0xffffffffu, sc[kf][2], s2);
                float t31 = __shfl_sync(0xffffffffu, sc[kf][3], s2);
                sc[kf][0] = odd ? t01 : t00;
                sc[kf][1] = odd ? t11 : t10;
                sc[kf][2] = odd ? t21 : t20;
                sc[kf][3] = odd ? t31 : t30;
            }
        }

        // ---- GEMM2: O += P V via ldmatrix on V^T ----
#pragma unroll
        for (int nfp = 0; nfp < 4; nfp++) {
            const int nf = 2 * nfp + g2_nfoff;
            const uint32_t base = sb + VT + (uint32_t)(nf * 8 + g2_r) * VTSTR + g2_half16;
#pragma unroll
            for (int kf = 0; kf < 8; kf++) {
                uint32_t b0, b1, b2, b3;
                ldm4(b0, b1, b2, b3, base + (uint32_t)kf * 32);
                mma_tf32(oc[2 * nfp],
                         __float_as_uint(sc[kf][0]), __float_as_uint(sc[kf][1]),
                         __float_as_uint(sc[kf][2]), __float_as_uint(sc[kf][3]), b0, b1);
                mma_tf32(oc[2 * nfp + 1],
                         __float_as_uint(sc[kf][0]), __float_as_uint(sc[kf][1]),
                         __float_as_uint(sc[kf][2]), __float_as_uint(sc[kf][3]), b2, b3);
            }
        }

        CPA_WAIT(0);          // K(t+1) + V(t+1) landed
        if (t + 1 < NT) {     // K-rewrite (own chunks) before sync B
            const uint32_t sKn = sb + (uint32_t)((t + 1) & 1) * KT;
#pragma unroll
            for (int i = 0; i < 4; i++) {
                int idx = tid + i * NTH;
                uint32_t ak = sKn + (idx >> 4) * KSTR + (idx & 15) * 16;
                float4 f = lds128f(ak);
                sts128u(ak, tf32rna(f.x), tf32rna(f.y), tf32rna(f.z), tf32rna(f.w));
            }
        }
        __syncthreads();      // sync B: GEMM2 V^T reads done; V-orig(t+1) visible
        if (t + 1 < NT) {     // transpose V(t+1) -> V^T (with rna)
#pragma unroll
            for (int i = 0; i < 4; i++) {
                int kvb = tr_kvq + 4 * i;
                uint32_t s = tr_src_col + (uint32_t)kvb * 256;
                float f0 = ldsf(s), f1 = ldsf(s + 256), f2 = ldsf(s + 512), f3 = ldsf(s + 768);
                sts128u(tr_dst_row + (uint32_t)kvb * 4,
                        tf32rna(f0), tf32rna(f1), tf32rna(f2), tf32rna(f3));
            }
        }
    }

    // ---- epilogue: quad row sums + normalize + store ----
    l0 += __shfl_xor_sync(0xffffffffu, l0, 1);
    l0 += __shfl_xor_sync(0xffffffffu, l0, 2);
    l1 += __shfl_xor_sync(0xffffffffu, l1, 1);
    l1 += __shfl_xor_sync(0xffffffffu, l1, 2);
    const float inv0 = 1.f / l0;
    const float inv1 = 1.f / l1;

    float* orow0 = Ob + (size_t)(w * 16 + r4) * D_ + 2 * q4;
    float* orow1 = orow0 + 8 * D_;
#pragma unroll
    for (int nf = 0; nf < 8; nf++) {
        float2 v0 = make_float2(oc[nf][0] * inv0, oc[nf][1] * inv0);
        float2 v1 = make_float2(oc[nf][2] * inv1, oc[nf][3] * inv1);
        *(float2*)(orow0 + nf * 8) = v0;
        *(float2*)(orow1 + nf * 8) = v1;
    }
}

extern "C" void kernel_launch(void* const* d_in, const int* in_sizes, int n_in,
                              void* d_out, int out_size) {
    const float* q = (const float*)d_in[0];
    const float* k = (const float*)d_in[1];
    const float* v = (const float*)d_in[2];
    const int*   m = (const int*)d_in[3];
    float* o = (float*)d_out;

    cudaFuncSetAttribute(attn_hmma, cudaFuncAttributeMaxDynamicSharedMemorySize, SMEM_BYTES);
    dim3 grid(TO_ / BM, B_);
    attn_hmma<<<grid, NTH, SMEM_BYTES>>>(q, k, v, m, o);
}

// round 17
// speedup vs baseline: 1.3778x; 1.3778x over previous
#include <cuda_runtime.h>
#include <math.h>
#include <stdint.h>

#define B_   16
#define TO_  2048
#define TI_  2048
#define D_   64
#define BM   128
#define BN   64
#define NTH  256
#define NT   (TI_/BN)

// smem layout (bytes):
//  K buf0 @ 0      : 64 rows * 272B = 17408  (ldmatrix conflict-free)
//  K buf1 @ 17408
//  V^T b0 @ 34816  : 64 d-rows * 272B = 17408 ([d][kv], ldmatrix conflict-free)
//  V^T b1 @ 52224
//  mask   @ 69632  : 128 rows * 272B = 34816
#define KSTR   272
#define KT     17408
#define VT0    34816
#define VTSTR  272
#define SM_M   69632
#define SMEM_BYTES (69632 + 34816)   // 104448

#define QSCALE 0.18033688011112042f  // 0.125 * log2(e)

#define CPA16(dst, src) asm volatile("cp.async.cg.shared.global [%0], [%1], 16;" :: "r"(dst), "l"(src))
#define CPA4(dst, src)  asm volatile("cp.async.ca.shared.global [%0], [%1], 4;"  :: "r"(dst), "l"(src))
#define CPA_COMMIT()    asm volatile("cp.async.commit_group;" ::: "memory")
#define CPA_WAIT(n)     asm volatile("cp.async.wait_group %0;" :: "n"(n) : "memory")

static __device__ __forceinline__ uint32_t smem_u32(const void* p) {
    uint32_t a;
    asm("{ .reg .u64 t; cvta.to.shared.u64 t, %1; cvt.u32.u64 %0, t; }" : "=r"(a) : "l"(p));
    return a;
}
static __device__ __forceinline__ uint32_t tf32rna(float x) {
    uint32_t r; asm("cvt.rna.tf32.f32 %0, %1;" : "=r"(r) : "f"(x)); return r;
}
static __device__ __forceinline__ float ex2f(float x) {
    float y; asm("ex2.approx.ftz.f32 %0, %1;" : "=f"(y) : "f"(x)); return y;
}
static __device__ __forceinline__ int2 lds64i(uint32_t a) {
    int2 v; asm volatile("ld.shared.v2.b32 {%0,%1}, [%2];" : "=r"(v.x), "=r"(v.y) : "r"(a)); return v;
}
static __device__ __forceinline__ float4 lds128f(uint32_t a) {
    float4 v;
    asm volatile("ld.shared.v4.f32 {%0,%1,%2,%3}, [%4];"
                 : "=f"(v.x), "=f"(v.y), "=f"(v.z), "=f"(v.w) : "r"(a));
    return v;
}
static __device__ __forceinline__ void sts128u(uint32_t a, uint32_t x, uint32_t y,
                                               uint32_t z, uint32_t w) {
    asm volatile("st.shared.v4.b32 [%0], {%1,%2,%3,%4};"
                 :: "r"(a), "r"(x), "r"(y), "r"(z), "r"(w) : "memory");
}
static __device__ __forceinline__ void ldm4(uint32_t& r0, uint32_t& r1, uint32_t& r2,
                                            uint32_t& r3, uint32_t a) {
    asm volatile("ldmatrix.sync.aligned.m8n8.x4.shared.b16 {%0,%1,%2,%3}, [%4];"
                 : "=r"(r0), "=r"(r1), "=r"(r2), "=r"(r3) : "r"(a));
}
static __device__ __forceinline__ void mma_tf32(float* c, uint32_t a0, uint32_t a1,
                                                uint32_t a2, uint32_t a3,
                                                uint32_t b0, uint32_t b1) {
    asm volatile(
        "mma.sync.aligned.m16n8k8.row.col.f32.tf32.tf32.f32 "
        "{%0,%1,%2,%3}, {%4,%5,%6,%7}, {%8,%9}, {%0,%1,%2,%3};"
        : "+f"(c[0]), "+f"(c[1]), "+f"(c[2]), "+f"(c[3])
        : "r"(a0), "r"(a1), "r"(a2), "r"(a3), "r"(b0), "r"(b1));
}

__global__ __launch_bounds__(NTH, 2)
void attn_hmma(const float* __restrict__ Q, const float* __restrict__ K,
               const float* __restrict__ V, const int* __restrict__ M,
               float* __restrict__ O)
{
    extern __shared__ char smem[];
    const uint32_t sb = smem_u32(smem);
    const int tid  = threadIdx.x;
    const int w    = tid >> 5;
    const int lane = tid & 31;
    const int q4   = lane & 3;        // quad lane
    const int r4   = lane >> 2;       // 0..7
    const int b    = blockIdx.y;
    const int q0   = blockIdx.x * BM;

    const float* Qb = Q + ((size_t)b * TO_ + q0) * D_;
    const float* Kb = K + (size_t)b * TI_ * D_;
    const float* Vb = V + (size_t)b * TI_ * D_;
    const int*   Mb = M + ((size_t)b * TO_ + q0) * TI_;
    float*       Ob = O + ((size_t)b * TO_ + q0) * D_;

    // V^T transpose-copy assignment: warp covers kv rows w*8..w*8+7, lane = d base
    const int vkv0 = (tid >> 5) * 8;
    const int vd0  = tid & 31;

    // ---- stage K(0) + V^T(0) into buffer 0 ----
#pragma unroll
    for (int i = 0; i < 4; i++) {
        int idx = tid + i * NTH;            // 0..1023 chunk ids
        CPA16(sb + (idx >> 4) * KSTR + (idx & 15) * 16,
              (const char*)(Kb + (size_t)(idx >> 4) * D_) + (idx & 15) * 16);
    }
#pragma unroll
    for (int i = 0; i < 16; i++) {
        int kv = vkv0 + (i >> 1);
        int d  = vd0 + 32 * (i & 1);
        CPA4(sb + VT0 + (uint32_t)d * VTSTR + (uint32_t)kv * 4,
             (const char*)(Vb + (size_t)kv * D_ + d));
    }
    CPA_COMMIT();

    // ---- Q fragments (once, scale*log2e folded, tf32 rna) ----
    uint32_t qa[8][4];
    {
        const float* qp = Qb + (size_t)(w * 16 + r4) * D_ + q4;
#pragma unroll
        for (int kf = 0; kf < 8; kf++) {
            qa[kf][0] = tf32rna(QSCALE * qp[kf * 8]);
            qa[kf][1] = tf32rna(QSCALE * qp[kf * 8 + 8 * D_]);
            qa[kf][2] = tf32rna(QSCALE * qp[kf * 8 + 4]);
            qa[kf][3] = tf32rna(QSCALE * qp[kf * 8 + 4 + 8 * D_]);
        }
    }

    float oc[8][4];
#pragma unroll
    for (int nf = 0; nf < 8; nf++)
#pragma unroll
        for (int i = 0; i < 4; i++) oc[nf][i] = 0.f;
    float l0 = 0.f, l1 = 0.f;

    // GEMM1 ldmatrix per-thread row (272B stride, conflict-free)
    const uint32_t ldmc = (uint32_t)(lane & 7) * KSTR + (uint32_t)((lane >> 3) & 1) * 16
                        + (uint32_t)(lane >> 4) * (8 * KSTR);

    // GEMM2 ldmatrix geometry on V^T: matrix m = lane>>3 -> (nf = 2*nfp + (m>>1), half = m&1)
    const int g2_m  = lane >> 3;
    const int g2_r  = lane & 7;
    const uint32_t g2_half16 = (uint32_t)(g2_m & 1) * 16;
    const int g2_nfoff = g2_m >> 1;       // 0 or 1

    CPA_WAIT(0);
    // K(0) rewrite to tf32-rna (own chunks, self-visible)
#pragma unroll
    for (int i = 0; i < 4; i++) {
        int idx = tid + i * NTH;
        uint32_t ak = sb + (idx >> 4) * KSTR + (idx & 15) * 16;
        float4 f = lds128f(ak);
        sts128u(ak, tf32rna(f.x), tf32rna(f.y), tf32rna(f.z), tf32rna(f.w));
    }
    __syncthreads();                      // K(0) rewritten + V^T(0) visible

    for (int t = 0; t < NT; t++) {
        const uint32_t sK  = sb + (uint32_t)(t & 1) * KT;
        const uint32_t sVT = sb + VT0 + (uint32_t)(t & 1) * KT;

        // ---- stage mask(t) — group 1 ----
        {
            const char* Mg = (const char*)(Mb + (size_t)t * BN);
#pragma unroll
            for (int i = 0; i < 8; i++) {
                int chunk = tid + i * NTH;   // 128 rows x 16 chunks
                CPA16(sb + SM_M + (chunk >> 4) * 272 + (chunk & 15) * 16,
                      Mg + (size_t)(chunk >> 4) * (TI_ * 4) + (chunk & 15) * 16);
            }
        }
        CPA_COMMIT();
        // ---- stage K(t+1) + V^T(t+1) — group 2 ----
        if (t + 1 < NT) {
            const uint32_t sKn  = sb + (uint32_t)((t + 1) & 1) * KT;
            const uint32_t sVTn = sb + VT0 + (uint32_t)((t + 1) & 1) * KT;
            const float* Kg = Kb + (size_t)(t + 1) * BN * D_;
            const float* Vg = Vb + (size_t)(t + 1) * BN * D_;
#pragma unroll
            for (int i = 0; i < 4; i++) {
                int idx = tid + i * NTH;
                CPA16(sKn + (idx >> 4) * KSTR + (idx & 15) * 16,
                      (const char*)(Kg + (size_t)(idx >> 4) * D_) + (idx & 15) * 16);
            }
#pragma unroll
            for (int i = 0; i < 16; i++) {
                int kv = vkv0 + (i >> 1);
                int d  = vd0 + 32 * (i & 1);
                CPA4(sVTn + (uint32_t)d * VTSTR + (uint32_t)kv * 4,
                     (const char*)(Vg + (size_t)kv * D_ + d));
            }
        }
        CPA_COMMIT();

        // ---- GEMM1: S = Q K^T (ldmatrix.x4) ----
        float sc[8][4];
#pragma unroll
        for (int nf = 0; nf < 8; nf++)
#pragma unroll
            for (int i = 0; i < 4; i++) sc[nf][i] = 0.f;

#pragma unroll
        for (int kf = 0; kf < 8; kf++) {
#pragma unroll
            for (int nfp = 0; nfp < 4; nfp++) {
                uint32_t b0, b1, b2, b3;
                ldm4(b0, b1, b2, b3, sK + ldmc + (uint32_t)nfp * (16 * KSTR) + (uint32_t)kf * 32);
                mma_tf32(sc[2 * nfp],     qa[kf][0], qa[kf][1], qa[kf][2], qa[kf][3], b0, b1);
                mma_tf32(sc[2 * nfp + 1], qa[kf][0], qa[kf][1], qa[kf][2], qa[kf][3], b2, b3);
            }
        }

        CPA_WAIT(1);          // mask staged (K/V^T prefetch still in flight)
        __syncthreads();      // sync A: mask visible

        // ---- mask + exp2 + tf32-rna (l from ROUNDED p) ----
        {
            const uint32_t mbase = sb + SM_M + (uint32_t)(w * 16 + r4) * 272 + (uint32_t)(2 * q4) * 4;
#pragma unroll
            for (int nf = 0; nf < 8; nf++) {
                const uint32_t ma = mbase + nf * 32;
                const int2 mlo = lds64i(ma);
                const int2 mhi = lds64i(ma + 8 * 272);
                float p0 = (mlo.x != 0) ? ex2f(sc[nf][0]) : 0.f;
                float p1 = (mlo.y != 0) ? ex2f(sc[nf][1]) : 0.f;
                float p2 = (mhi.x != 0) ? ex2f(sc[nf][2]) : 0.f;
                float p3 = (mhi.y != 0) ? ex2f(sc[nf][3]) : 0.f;
                p0 = __uint_as_float(tf32rna(p0));
                p1 = __uint_as_float(tf32rna(p1));
                p2 = __uint_as_float(tf32rna(p2));
                p3 = __uint_as_float(tf32rna(p3));
                l0 += p0 + p1;
                l1 += p2 + p3;
                sc[nf][0] = p0; sc[nf][1] = p1; sc[nf][2] = p2; sc[nf][3] = p3;
            }
        }

        // ---- P C-frag -> A-frag permutation (in place) ----
        {
            const int s0 = (lane & ~3) | (q4 >> 1);
            const int s2 = s0 + 2;
            const bool odd = (q4 & 1) != 0;
#pragma unroll
            for (int kf = 0; kf < 8; kf++) {
                float t00 = __shfl_sync(0xffffffffu, sc[kf][0], s0);
                float t01 = __shfl_sync(0xffffffffu, sc[kf][1], s0);
                float t10 = __shfl_sync(0xffffffffu, sc[kf][2], s0);
                float t11 = __shfl_sync(0xffffffffu, sc[kf][3], s0);
                float t20 = __shfl_sync(0xffffffffu, sc[kf][0], s2);
                float t21 = __shfl_sync(0xffffffffu, sc[kf][1], s2);
                float t30 = __shfl_sync(0xffffffffu, sc[kf][2], s2);
                float t31 = __shfl_sync(0xffffffffu, sc[kf][3], s2);
                sc[kf][0] = odd ? t01 : t00;
                sc[kf][1] = odd ? t11 : t10;
                sc[kf][2] = odd ? t21 : t20;
                sc[kf][3] = odd ? t31 : t30;
            }
        }

        // ---- GEMM2: O += P V via ldmatrix on V^T ----
#pragma unroll
        for (int nfp = 0; nfp < 4; nfp++) {
            const int nf = 2 * nfp + g2_nfoff;
            const uint32_t base = sVT + (uint32_t)(nf * 8 + g2_r) * VTSTR + g2_half16;
#pragma unroll
            for (int kf = 0; kf < 8; kf++) {
                uint32_t b0, b1, b2, b3;
                ldm4(b0, b1, b2, b3, base + (uint32_t)kf * 32);
                mma_tf32(oc[2 * nfp],
                         __float_as_uint(sc[kf][0]), __float_as_uint(sc[kf][1]),
                         __float_as_uint(sc[kf][2]), __float_as_uint(sc[kf][3]), b0, b1);
                mma_tf32(oc[2 * nfp + 1],
                         __float_as_uint(sc[kf][0]), __float_as_uint(sc[kf][1]),
                         __float_as_uint(sc[kf][2]), __float_as_uint(sc[kf][3]), b2, b3);
            }
        }

        CPA_WAIT(0);          // K(t+1) + V^T(t+1) landed
        if (t + 1 < NT) {     // K-rewrite to tf32-rna (own chunks)
            const uint32_t sKn = sb + (uint32_t)((t + 1) & 1) * KT;
#pragma unroll
            for (int i = 0; i < 4; i++) {
                int idx = tid + i * NTH;
                uint32_t ak = sKn + (idx >> 4) * KSTR + (idx & 15) * 16;
                float4 f = lds128f(ak);
                sts128u(ak, tf32rna(f.x), tf32rna(f.y), tf32rna(f.z), tf32rna(f.w));
            }
        }
        __syncthreads();      // sync B: publish K(t+1)/V^T(t+1); mask reusable
    }

    // ---- epilogue: quad row sums + normalize + store ----
    l0 += __shfl_xor_sync(0xffffffffu, l0, 1);
    l0 += __shfl_xor_sync(0xffffffffu, l0, 2);
    l1 += __shfl_xor_sync(0xffffffffu, l1, 1);
    l1 += __shfl_xor_sync(0xffffffffu, l1, 2);
    const float inv0 = 1.f / l0;
    const float inv1 = 1.f / l1;

    float* orow0 = Ob + (size_t)(w * 16 + r4) * D_ + 2 * q4;
    float* orow1 = orow0 + 8 * D_;
#pragma unroll
    for (int nf = 0; nf < 8; nf++) {
        float2 v0 = make_float2(oc[nf][0] * inv0, oc[nf][1] * inv0);
        float2 v1 = make_float2(oc[nf][2] * inv1, oc[nf][3] * inv1);
        *(float2*)(orow0 + nf * 8) = v0;
        *(float2*)(orow1 + nf * 8) = v1;
    }
}

extern "C" void kernel_launch(void* const* d_in, const int* in_sizes, int n_in,
                              void* d_out, int out_size) {
    const float* q = (const float*)d_in[0];
    const float* k = (const float*)d_in[1];
    const float* v = (const float*)d_in[2];
    const int*   m = (const int*)d_in[3];
    float* o = (float*)d_out;

    cudaFuncSetAttribute(attn_hmma, cudaFuncAttributeMaxDynamicSharedMemorySize, SMEM_BYTES);
    dim3 grid(TO_ / BM, B_);
    attn_hmma<<<grid, NTH, SMEM_BYTES>>>(q, k, v, m, o);
}